// round 9
// baseline (speedup 1.0000x reference)
#include <cuda_runtime.h>
#include <cstdint>

#define N_ATOMS 1024
#define NSHIFT 27
#define CUT2 25.0f                      // CUTOFF^2

#define ITILE 8                         // i-rows per block
#define JTILE 64                        // j-atoms per block
#define BTHREADS 256
#define PAIRS_TILE (JTILE * NSHIFT)     // 1728 pairs per row segment
#define UNITS (PAIRS_TILE / 4)          // 432 units of 4 pairs (12 floats)
#define NU 2                            // units per thread (432 <= 2*256)
#define SEG_FLOATS (PAIRS_TILE * 3)     // 5184 floats
#define SEG_BYTES (SEG_FLOATS * 4)      // 20736 B per TMA op (16B multiple)
#define NBUF 2                          // double-buffered big segments

// Fused kernel at the LTS write ceiling: register-resident B vectors
// (2 units x 4 consecutive pairs per thread), SMEM staging via STS.128,
// double-buffered 20736B cp.async.bulk stores.
__global__ void __launch_bounds__(BTHREADS)
radius_out(const float* __restrict__ frac,
           const float* __restrict__ cell,
           float* __restrict__ out) {
    __shared__ __align__(16) float buf[NBUF][SEG_FLOATS];   // 2 x 20736 B

    const int j0  = blockIdx.x * JTILE;    // x = j-segment: consecutive blocks
    const int i0  = blockIdx.y * ITILE;    //     write adjacent GMEM bands
    const int tid = threadIdx.x;

    float c[9];
#pragma unroll
    for (int m = 0; m < 9; m++) c[m] = __ldg(cell + m);

    // Per-thread B vectors for units u = tid + 256*k, pairs 4u..4u+3.
    // B[p] = cart[j0 + p/27] + shift(p%27) @ cell, identical FP order to ref.
    float Bx[NU][4], By[NU][4], Bz[NU][4];
#pragma unroll
    for (int k = 0; k < NU; k++) {
        int u = tid + BTHREADS * k;
        if (u < UNITS) {
#pragma unroll
            for (int q = 0; q < 4; q++) {
                int p = 4 * u + q;
                int j = p / NSHIFT;
                int s = p - NSHIFT * j;
                float f0 = __ldg(frac + 3 * (j0 + j) + 0);
                float f1 = __ldg(frac + 3 * (j0 + j) + 1);
                float f2 = __ldg(frac + 3 * (j0 + j) + 2);
                float sx = (float)(s / 9 - 1);
                float sy = (float)((s / 3) % 3 - 1);
                float sz = (float)(s % 3 - 1);
                float cj[3], sc[3];
#pragma unroll
                for (int m = 0; m < 3; m++) {
                    cj[m] = fmaf(f2, c[6 + m], fmaf(f1, c[3 + m], f0 * c[m]));
                    sc[m] = fmaf(sz, c[6 + m], fmaf(sy, c[3 + m], sx * c[m]));
                }
                Bx[k][q] = __fadd_rn(cj[0], sc[0]);
                By[k][q] = __fadd_rn(cj[1], sc[1]);
                Bz[k][q] = __fadd_rn(cj[2], sc[2]);
            }
        }
    }

#pragma unroll 1
    for (int r = 0; r < ITILE; r++) {
        const int b = r & (NBUF - 1);
        const int i = i0 + r;

        // Buffer b was handed to a bulk group at iteration r-2; allow the
        // younger group to stay in flight.
        if (r >= NBUF) {
            if (tid == 0)
                asm volatile("cp.async.bulk.wait_group 1;" ::: "memory");
            __syncthreads();
        }

        // cart[i], same fmaf chain as reference (broadcast loads)
        float g0 = __ldg(frac + 3 * i + 0);
        float g1 = __ldg(frac + 3 * i + 1);
        float g2 = __ldg(frac + 3 * i + 2);
        float cix = fmaf(g2, c[6], fmaf(g1, c[3], g0 * c[0]));
        float ciy = fmaf(g2, c[7], fmaf(g1, c[4], g0 * c[1]));
        float ciz = fmaf(g2, c[8], fmaf(g1, c[5], g0 * c[2]));

#pragma unroll
        for (int k = 0; k < NU; k++) {
            int u = tid + BTHREADS * k;
            if (u < UNITS) {
                float o[12];
#pragma unroll
                for (int q = 0; q < 4; q++) {
                    float dx = __fadd_rn(Bx[k][q], -cix);
                    float dy = __fadd_rn(By[k][q], -ciy);
                    float dz = __fadd_rn(Bz[k][q], -ciz);
                    float d2 = __fadd_rn(__fadd_rn(__fmul_rn(dx, dx),
                                                   __fmul_rn(dy, dy)),
                                         __fmul_rn(dz, dz));
                    bool keep = d2 < CUT2;   // self-edge yields +0 anyway
                    o[3 * q + 0] = keep ? dx : 0.0f;
                    o[3 * q + 1] = keep ? dy : 0.0f;
                    o[3 * q + 2] = keep ? dz : 0.0f;
                }
                // 12 consecutive floats -> 3x STS.128 (16B-aligned)
                float4* dst = (float4*)&buf[b][12 * u];
                dst[0] = make_float4(o[0], o[1],  o[2],  o[3]);
                dst[1] = make_float4(o[4], o[5],  o[6],  o[7]);
                dst[2] = make_float4(o[8], o[9],  o[10], o[11]);
            }
        }
        __syncthreads();

        if (tid == 0) {
            asm volatile("fence.proxy.async.shared::cta;" ::: "memory");
            // contiguous 20736B segment: out[(i*1024 + j0)*81 ...]
            float* gdst = out + (size_t)((size_t)i * N_ATOMS + (size_t)j0) * 81u;
            uint32_t ssrc = (uint32_t)__cvta_generic_to_shared(&buf[b][0]);
            asm volatile(
                "cp.async.bulk.global.shared::cta.bulk_group [%0], [%1], %2;"
                :: "l"(gdst), "r"(ssrc), "r"((uint32_t)SEG_BYTES)
                : "memory");
            asm volatile("cp.async.bulk.commit_group;" ::: "memory");
        }
    }

    // Drain all outstanding bulk stores before SMEM is released.
    if (tid == 0)
        asm volatile("cp.async.bulk.wait_group 0;" ::: "memory");
}

extern "C" void kernel_launch(void* const* d_in, const int* in_sizes, int n_in,
                              void* d_out, int out_size) {
    const float* frac = (const float*)d_in[0];   // [1024,3]
    const float* cell = (const float*)d_in[1];   // [3,3]
    float* out = (float*)d_out;                  // [1024,1024,27,3]

    dim3 grid(N_ATOMS / JTILE, N_ATOMS / ITILE); // (16, 128) = 2048 blocks
    radius_out<<<grid, BTHREADS>>>(frac, cell, out);
}